// round 16
// baseline (speedup 1.0000x reference)
#include <cuda_runtime.h>
#include <cuda_fp16.h>
#include <cstdint>

// Neural CA update via mma.sync fp16 GEMMs, v8:
// v7 (168us) + (1) ds partials in a DEDICATED smem region -> post-GEMM1
// __syncthreads removed (3 barriers/tile instead of 4); (2) loop-invariant W2
// B-fragments hoisted to registers (LDSM once, not per tile).

#define BATCH 16
#define CH 16
#define HH 256
#define WW 256
#define BDIM 256
#define NCTA 296              /* 148 SMs x 2 CTAs, exactly one wave */

// ---- dynamic shared memory layout (bytes) ----
#define SM_TILE0  0                        /* 16*6*34*4 = 13056 */
#define SM_TILE1  13056
#define SM_A1     26112                    /* A fp16: 128 rows x 128B */
#define SM_DS0    (SM_A1 + 16384)          /* ds k-half-0 partials, 16KB (dedicated) */
#define SM_DS1    (SM_DS0 + 16384)         /* ds k-half-1 partials, 16KB */
#define SM_W1     (SM_DS1 + 16384)         /* w1 fp16 [128 n][64 k], 128B pitch */
#define SM_W2     (SM_W1 + 16384)          /* w2 fp16 [16 n][128 k], 256B pitch */
#define SM_B1     (SM_W2 + 4096)
#define SM_B2     (SM_B1 + 512)
#define SM_TOTAL  (SM_B2 + 64)             /* ~96KB -> still 2 CTAs/SM */

#define SW128(x) ((x) ^ (((x) >> 3) & 0x70))
#define SWW2(x)  ((x) ^ ((((x) >> 8) & 7) << 4))

__device__ __forceinline__ uint32_t smem_u32(const void* p) {
    uint32_t a;
    asm("{ .reg .u64 t; cvta.to.shared.u64 t, %1; cvt.u32.u64 %0, t; }" : "=r"(a) : "l"(p));
    return a;
}

#define LDSM4(r0, r1, r2, r3, addr) \
    asm volatile("ldmatrix.sync.aligned.m8n8.x4.shared.b16 {%0,%1,%2,%3}, [%4];" \
                 : "=r"(r0), "=r"(r1), "=r"(r2), "=r"(r3) : "r"(addr))

#define MMAF16(d, a0, a1, a2, a3, b0, b1) \
    asm volatile("mma.sync.aligned.m16n8k16.row.col.f32.f16.f16.f32 " \
                 "{%0,%1,%2,%3}, {%4,%5,%6,%7}, {%8,%9}, {%0,%1,%2,%3};" \
                 : "+f"((d)[0]), "+f"((d)[1]), "+f"((d)[2]), "+f"((d)[3]) \
                 : "r"(a0), "r"(a1), "r"(a2), "r"(a3), "r"(b0), "r"(b1))

// pack two f32 -> f16x2 {lo=v0, hi=v1}
__device__ __forceinline__ uint32_t pack_f16x2(float v0, float v1) {
    uint32_t r;
    asm("cvt.rn.f16x2.f32 %0, %1, %2;" : "=r"(r) : "f"(v1), "f"(v0));
    return r;
}

__device__ __forceinline__ void cp4(uint32_t dst, const float* src, bool ok) {
    asm volatile("cp.async.ca.shared.global [%0], [%1], 4, %2;"
                 :: "r"(dst), "l"(src), "r"(ok ? 4u : 0u));
}
#define CP_COMMIT() asm volatile("cp.async.commit_group;" ::: "memory")
#define CP_WAIT0()  asm volatile("cp.async.wait_group 0;" ::: "memory")

__device__ float g_alpha[BATCH * HH * WW];

__device__ __forceinline__ void prefetch_tile(uint32_t tile_smem, int tg,
                                              const float* __restrict__ state, int tid) {
    const int b  = tg >> 9;
    const int rr = tg & 511;
    const int by = (rr >> 3) * 4;
    const int bx = (rr & 7) * 32;
    const float* sbp = state + (size_t)b * CH * HH * WW;
    for (int i = tid; i < CH * 6 * 34; i += BDIM) {
        const int c  = i / 204;
        const int r2 = i % 204;
        const int yy = r2 / 34;
        const int xx = r2 % 34;
        const int gy = by + yy - 1;
        const int gx = bx + xx - 1;
        const bool ok = (gy >= 0 && gy < HH && gx >= 0 && gx < WW);
        const float* src = ok ? (sbp + (c * HH + gy) * WW + gx) : sbp;
        cp4(tile_smem + (uint32_t)i * 4, src, ok);
    }
    CP_COMMIT();
}

__global__ void __launch_bounds__(BDIM, 2) nca_main_kernel(
    const float* __restrict__ state,
    const float* __restrict__ rand_u,
    const float* __restrict__ w1,
    const float* __restrict__ b1,
    const float* __restrict__ w2,
    const float* __restrict__ b2,
    float* __restrict__ out)
{
    extern __shared__ char smem[];
    const uint32_t sb32 = smem_u32(smem);
    const int tid  = threadIdx.x;
    const int wid  = tid >> 5;
    const int lane = tid & 31;

    // ---- stage weights: single fp16 ----
    for (int i = tid; i < 128 * 48; i += BDIM) {
        const int o = i / 48, k = i - o * 48;
        const uint32_t sw = SW128((uint32_t)(o * 128 + k * 2));
        *(__half*)(smem + SM_W1 + sw) = __float2half_rn(w1[i]);
    }
    for (int i = tid; i < 16 * 128; i += BDIM) {
        const int r = i >> 7, k = i & 127;
        const uint32_t sw = SWW2((uint32_t)(r * 256 + k * 2));
        *(__half*)(smem + SM_W2 + sw) = __float2half_rn(w2[i]);
    }
    float* s_b1 = (float*)(smem + SM_B1);
    float* s_b2 = (float*)(smem + SM_B2);
    if (tid < 128) s_b1[tid] = b1[tid];
    if (tid < CH)  s_b2[tid] = b2[tid];

    // warp roles: m-group = wid&3 (32 pixel-rows), n/k-half = wid>>2
    const int mg = wid & 3;
    const int nh = wid >> 2;
    const int mrow = mg << 5;

    // per-thread pixel/channel split for perception & epilogue
    const int p     = tid & 127;
    const int chalf = tid >> 7;
    const int c0    = chalf * 8;
    const int lx = p & 31;
    const int ly = p >> 5;

    const uint32_t A1  = sb32 + SM_A1;
    const uint32_t W1S = sb32 + SM_W1;
    const uint32_t W2S = sb32 + SM_W2;

    const int amat  = lane >> 3;
    const int arow_off = (lane & 7) + 8 * (amat & 1);
    const int acol_off = 8 * (amat >> 1);
    const int brow_off = (lane & 7) + 8 * (amat >> 1);
    const int bcol_off = 8 * (amat & 1);

    // balanced contiguous tile range: 200 CTAs x 28 + 96 CTAs x 27 = 8192
    const int bid  = (int)blockIdx.x;
    const int cnt  = 27 + (bid < 200 ? 1 : 0);
    const int base = bid * 27 + (bid < 200 ? bid : 200);

    __syncthreads();   // W2 staged before hoisted LDSM below

    // ---- hoist loop-invariant W2 B-fragments (4 LDSM4 = 16 regs) ----
    uint32_t w2f[4][4];
#pragma unroll
    for (int ks = 0; ks < 4; ks++) {
        const uint32_t bbyte = (uint32_t)(brow_off * 256 + (64 * nh + ks * 16 + bcol_off) * 2);
        LDSM4(w2f[ks][0], w2f[ks][1], w2f[ks][2], w2f[ks][3], W2S + SWW2(bbyte));
    }

    prefetch_tile(sb32 + SM_TILE0, base, state, tid);

#pragma unroll 1
    for (int t = 0; t < cnt; t++) {
        const int tg = base + t;
        const int b  = tg >> 9;
        const int rr = tg & 511;
        const int by = (rr >> 3) * 4;
        const int bx = (rr & 7) * 32;
        const uint32_t tile_off = (t & 1) ? SM_TILE1 : SM_TILE0;
        const float* s_tile = (const float*)(smem + tile_off);

        CP_WAIT0();
        __syncthreads();   // B1: tile ready; also orders prev-tile GEMM1 A1 reads vs new A1 writes

        // ---- perception: this thread's 8 channels of its pixel ----
        float a[24];
        float sv[8];
#pragma unroll
        for (int i = 0; i < 8; i++) {
            const float* tp = s_tile + (c0 + i) * 204;
            const float a00 = tp[(ly + 0) * 34 + lx + 0];
            const float a01 = tp[(ly + 0) * 34 + lx + 1];
            const float a02 = tp[(ly + 0) * 34 + lx + 2];
            const float a10 = tp[(ly + 1) * 34 + lx + 0];
            const float a11 = tp[(ly + 1) * 34 + lx + 1];
            const float a12 = tp[(ly + 1) * 34 + lx + 2];
            const float a20 = tp[(ly + 2) * 34 + lx + 0];
            const float a21 = tp[(ly + 2) * 34 + lx + 1];
            const float a22 = tp[(ly + 2) * 34 + lx + 2];
            a[3 * i + 0] = (a02 - a00) + 2.0f * (a12 - a10) + (a22 - a20);
            a[3 * i + 1] = (a20 - a00) + 2.0f * (a21 - a01) + (a22 - a02);
            a[3 * i + 2] = a11;
            sv[i] = a11;
        }
        // store 12 f16x2 pairs (features 24*chalf .. +23) into A1
        {
            const uint32_t rowb = (uint32_t)p * 128;
            const int rot = 3 * ((lane >> 3) & 3);
#pragma unroll
            for (int jj = 0; jj < 12; jj++) {
                int j = jj + rot; if (j >= 12) j -= 12;
                const uint32_t sw = SW128(rowb + (uint32_t)(chalf * 12 + j) * 4);
                *(uint32_t*)(smem + SM_A1 + sw) = pack_f16x2(a[2 * j], a[2 * j + 1]);
            }
        }

        if (t + 1 < cnt)
            prefetch_tile(sb32 + ((t & 1) ? SM_TILE0 : SM_TILE1), tg + 1, state, tid);

        __syncthreads();   // B2: A visible to all warps

        // ---- GEMM1: warp computes h[mrow..+31][64*nh..+63] = A * w1 ----
        float acc[2][8][4];
#pragma unroll
        for (int mt = 0; mt < 2; mt++)
#pragma unroll
            for (int nt = 0; nt < 8; nt++)
#pragma unroll
                for (int i = 0; i < 4; i++) acc[mt][nt][i] = 0.0f;

#pragma unroll
        for (int ks = 0; ks < 3; ks++) {
            uint32_t af[2][4];
#pragma unroll
            for (int mt = 0; mt < 2; mt++) {
                const uint32_t abyte = (uint32_t)((mrow + 16 * mt + arow_off) * 128
                                                  + (ks * 16 + acol_off) * 2);
                LDSM4(af[mt][0], af[mt][1], af[mt][2], af[mt][3], A1 + SW128(abyte));
            }
#pragma unroll
            for (int ntp = 0; ntp < 4; ntp++) {
                const uint32_t bbyte = (uint32_t)((64 * nh + ntp * 16 + brow_off) * 128
                                                  + (ks * 16 + bcol_off) * 2);
                uint32_t b0, b1, b2, b3;
                LDSM4(b0, b1, b2, b3, W1S + SW128(bbyte));
                MMAF16(acc[0][2 * ntp],     af[0][0], af[0][1], af[0][2], af[0][3], b0, b1);
                MMAF16(acc[0][2 * ntp + 1], af[0][0], af[0][1], af[0][2], af[0][3], b2, b3);
                MMAF16(acc[1][2 * ntp],     af[1][0], af[1][1], af[1][2], af[1][3], b0, b1);
                MMAF16(acc[1][2 * ntp + 1], af[1][0], af[1][1], af[1][2], af[1][3], b2, b3);
            }
        }

        // (no barrier: ds region is dedicated; GEMM1->GEMM2 is in-register, per-warp)

        // ---- GEMM2 (K-split): ds partial = relu(h+b1)_f16 * w2 ----
        float dsv[2][2][4];
#pragma unroll
        for (int mt = 0; mt < 2; mt++)
#pragma unroll
            for (int nt = 0; nt < 2; nt++)
#pragma unroll
                for (int i = 0; i < 4; i++) dsv[mt][nt][i] = 0.0f;

#pragma unroll
        for (int ks = 0; ks < 4; ks++) {
            uint32_t ah[2][4];
#pragma unroll
            for (int mt = 0; mt < 2; mt++) {
#pragma unroll
                for (int j = 0; j < 2; j++) {
                    const float* c = acc[mt][2 * ks + j];
                    const int col = 64 * nh + 16 * ks + 8 * j + 2 * (lane & 3);
                    const float bb0 = s_b1[col], bb1 = s_b1[col + 1];
                    const float v0 = fmaxf(c[0] + bb0, 0.0f);
                    const float v1 = fmaxf(c[1] + bb1, 0.0f);
                    const float v2 = fmaxf(c[2] + bb0, 0.0f);
                    const float v3 = fmaxf(c[3] + bb1, 0.0f);
                    ah[mt][2 * j]     = pack_f16x2(v0, v1);
                    ah[mt][2 * j + 1] = pack_f16x2(v2, v3);
                }
            }
#pragma unroll
            for (int mt = 0; mt < 2; mt++) {
                MMAF16(dsv[mt][0], ah[mt][0], ah[mt][1], ah[mt][2], ah[mt][3], w2f[ks][0], w2f[ks][1]);
                MMAF16(dsv[mt][1], ah[mt][0], ah[mt][1], ah[mt][2], ah[mt][3], w2f[ks][2], w2f[ks][3]);
            }
        }

        // ---- write ds partials (per k-half region, XOR-rotated rows) ----
        {
            const uint32_t dbase = nh ? SM_DS1 : SM_DS0;
#pragma unroll
            for (int mt = 0; mt < 2; mt++) {
                const int r0 = mrow + 16 * mt + (lane >> 2);
                const uint32_t x0 = ((uint32_t)(r0 & 7)) << 4;
#pragma unroll
                for (int nt = 0; nt < 2; nt++) {
                    const uint32_t cb = (uint32_t)(32 * nt + 8 * (lane & 3));
                    *(float2*)(smem + dbase + r0 * 128       + (cb ^ x0)) = make_float2(dsv[mt][nt][0], dsv[mt][nt][1]);
                    *(float2*)(smem + dbase + (r0 + 8) * 128 + (cb ^ x0)) = make_float2(dsv[mt][nt][2], dsv[mt][nt][3]);
                }
            }
        }
        __syncthreads();   // B3: ds partials visible

        // ---- epilogue: this thread's 8 channels of its pixel ----
        float dsval[8];
        {
            const uint32_t x0 = ((uint32_t)(p & 7)) << 4;
#pragma unroll
            for (int j = 0; j < 2; j++) {
                const uint32_t cb = ((uint32_t)(16 * (2 * chalf + j))) ^ x0;
                const float4 u = *(const float4*)(smem + SM_DS0 + p * 128 + cb);
                const float4 v = *(const float4*)(smem + SM_DS1 + p * 128 + cb);
                dsval[4 * j + 0] = u.x + v.x; dsval[4 * j + 1] = u.y + v.y;
                dsval[4 * j + 2] = u.z + v.z; dsval[4 * j + 3] = u.w + v.w;
            }
        }

        const int px = bx + lx;
        const int py = by + ly;
        const float* rb = rand_u + (size_t)b * CH * HH * WW;
        float* ob = out + (size_t)b * CH * HH * WW;
#pragma unroll
        for (int i = 0; i < 8; i++) {
            const int c = c0 + i;
            const int idx = (c * HH + py) * WW + px;
            const float m  = (rb[idx] < 0.5f) ? 1.0f : 0.0f;
            const float ds = dsval[i] + s_b2[c];
            const float ns = fmaf(ds, m, sv[i]);
            ob[idx] = ns;
            if (c == 3) g_alpha[((size_t)b * HH + py) * WW + px] = ns;
        }
    }
}

// Pass 2: 3x3 max-pool of alpha -> aliveness; zero dead pixels in-place.
__global__ __launch_bounds__(256) void nca_alive_kernel(float* __restrict__ out)
{
    const int gidx = blockIdx.x * blockDim.x + threadIdx.x;
    if (gidx >= BATCH * HH * WW) return;
    const int px = gidx & (WW - 1);
    const int py = (gidx >> 8) & (HH - 1);
    const int b  = gidx >> 16;

    const float* ap = g_alpha + (size_t)b * HH * WW;
    float m = -3.402823466e38f;
#pragma unroll
    for (int dy = -1; dy <= 1; dy++) {
        const int yy = py + dy;
        if (yy < 0 || yy >= HH) continue;
#pragma unroll
        for (int dx = -1; dx <= 1; dx++) {
            const int xx = px + dx;
            if (xx < 0 || xx >= WW) continue;
            m = fmaxf(m, ap[yy * WW + xx]);
        }
    }
    if (!(m > 0.1f)) {
        float* ob = out + (size_t)b * CH * HH * WW + py * WW + px;
#pragma unroll
        for (int c = 0; c < CH; c++) ob[c * HH * WW] = 0.0f;
    }
}

extern "C" void kernel_launch(void* const* d_in, const int* in_sizes, int n_in,
                              void* d_out, int out_size)
{
    const float* state  = (const float*)d_in[0];
    const float* rand_u = (const float*)d_in[1];
    const float* w1 = (const float*)d_in[3];
    const float* b1 = (const float*)d_in[4];
    const float* w2 = (const float*)d_in[5];
    const float* b2 = (const float*)d_in[6];
    float* out = (float*)d_out;

    cudaFuncSetAttribute(nca_main_kernel, cudaFuncAttributeMaxDynamicSharedMemorySize, SM_TOTAL);
    nca_main_kernel<<<NCTA, BDIM, SM_TOTAL>>>(state, rand_u, w1, b1, w2, b2, out);

    const int npix = BATCH * HH * WW;
    nca_alive_kernel<<<(npix + 255) / 256, 256>>>(out);
}

// round 17
// speedup vs baseline: 1.0376x; 1.0376x over previous
#include <cuda_runtime.h>
#include <cuda_fp16.h>
#include <cstdint>

// Neural CA update via mma.sync fp16 GEMMs, v9:
// WARP-LOCAL tile pipeline. Each warp owns 16 pixel-rows and does
// perception -> GEMM1 (m16 x n128 x k48) -> GEMM2 (m16 x n16 x k128)
// -> epilogue entirely within the warp (warp-private smem staging,
// __syncwarp only). ONE __syncthreads per tile (halo tile sharing).
// Warps desync across the tile body -> tensor pipe stays fed during
// any warp's scalar sections.

#define BATCH 16
#define CH 16
#define HH 256
#define WW 256
#define BDIM 256
#define NCTA 296              /* 148 SMs x 2 CTAs, exactly one wave */

// ---- dynamic shared memory layout (bytes) ----
#define SM_TILE0  0                        /* 16*6*34*4 = 13056 */
#define SM_TILE1  13056
#define SM_A1     26112                    /* per-warp A staging: 8 x 2048 */
#define SM_DS     42496                    /* per-warp ds staging: 8 x 1280 */
#define SM_W1     52736                    /* w1 fp16 [128 n][64 k], 128B pitch */
#define SM_W2     69120                    /* w2 fp16 [16 n][128 k], 256B pitch */
#define SM_B1     73216
#define SM_B2     73728
#define SM_TOTAL  73792                    /* ~72KB -> 2 CTAs/SM (reg-limited) */

#define DS_PITCH  18                       /* floats per row: 18 -> conflict-free rows */

#define SW128(x) ((x) ^ (((x) >> 3) & 0x70))
#define SWW2(x)  ((x) ^ ((((x) >> 8) & 7) << 4))

__device__ __forceinline__ uint32_t smem_u32(const void* p) {
    uint32_t a;
    asm("{ .reg .u64 t; cvta.to.shared.u64 t, %1; cvt.u32.u64 %0, t; }" : "=r"(a) : "l"(p));
    return a;
}

#define LDSM4(r0, r1, r2, r3, addr) \
    asm volatile("ldmatrix.sync.aligned.m8n8.x4.shared.b16 {%0,%1,%2,%3}, [%4];" \
                 : "=r"(r0), "=r"(r1), "=r"(r2), "=r"(r3) : "r"(addr))

#define MMAF16(d, a0, a1, a2, a3, b0, b1) \
    asm volatile("mma.sync.aligned.m16n8k16.row.col.f32.f16.f16.f32 " \
                 "{%0,%1,%2,%3}, {%4,%5,%6,%7}, {%8,%9}, {%0,%1,%2,%3};" \
                 : "+f"((d)[0]), "+f"((d)[1]), "+f"((d)[2]), "+f"((d)[3]) \
                 : "r"(a0), "r"(a1), "r"(a2), "r"(a3), "r"(b0), "r"(b1))

// pack two f32 -> f16x2 {lo=v0, hi=v1}
__device__ __forceinline__ uint32_t pack_f16x2(float v0, float v1) {
    uint32_t r;
    asm("cvt.rn.f16x2.f32 %0, %1, %2;" : "=r"(r) : "f"(v1), "f"(v0));
    return r;
}

__device__ __forceinline__ void cp4(uint32_t dst, const float* src, bool ok) {
    asm volatile("cp.async.ca.shared.global [%0], [%1], 4, %2;"
                 :: "r"(dst), "l"(src), "r"(ok ? 4u : 0u));
}
#define CP_COMMIT() asm volatile("cp.async.commit_group;" ::: "memory")
#define CP_WAIT0()  asm volatile("cp.async.wait_group 0;" ::: "memory")

__device__ float g_alpha[BATCH * HH * WW];

__device__ __forceinline__ void prefetch_tile(uint32_t tile_smem, int tg,
                                              const float* __restrict__ state, int tid) {
    const int b  = tg >> 9;
    const int rr = tg & 511;
    const int by = (rr >> 3) * 4;
    const int bx = (rr & 7) * 32;
    const float* sbp = state + (size_t)b * CH * HH * WW;
    for (int i = tid; i < CH * 6 * 34; i += BDIM) {
        const int c  = i / 204;
        const int r2 = i % 204;
        const int yy = r2 / 34;
        const int xx = r2 % 34;
        const int gy = by + yy - 1;
        const int gx = bx + xx - 1;
        const bool ok = (gy >= 0 && gy < HH && gx >= 0 && gx < WW);
        const float* src = ok ? (sbp + (c * HH + gy) * WW + gx) : sbp;
        cp4(tile_smem + (uint32_t)i * 4, src, ok);
    }
    CP_COMMIT();
}

__global__ void __launch_bounds__(BDIM, 2) nca_main_kernel(
    const float* __restrict__ state,
    const float* __restrict__ rand_u,
    const float* __restrict__ w1,
    const float* __restrict__ b1,
    const float* __restrict__ w2,
    const float* __restrict__ b2,
    float* __restrict__ out)
{
    extern __shared__ char smem[];
    const uint32_t sb32 = smem_u32(smem);
    const int tid  = threadIdx.x;
    const int wid  = tid >> 5;
    const int lane = tid & 31;

    // ---- stage weights: single fp16 ----
    for (int i = tid; i < 128 * 48; i += BDIM) {
        const int o = i / 48, k = i - o * 48;
        const uint32_t sw = SW128((uint32_t)(o * 128 + k * 2));
        *(__half*)(smem + SM_W1 + sw) = __float2half_rn(w1[i]);
    }
    for (int i = tid; i < 16 * 128; i += BDIM) {
        const int r = i >> 7, k = i & 127;
        const uint32_t sw = SWW2((uint32_t)(r * 256 + k * 2));
        *(__half*)(smem + SM_W2 + sw) = __float2half_rn(w2[i]);
    }
    float* s_b1 = (float*)(smem + SM_B1);
    float* s_b2 = (float*)(smem + SM_B2);
    if (tid < 128) s_b1[tid] = b1[tid];
    if (tid < CH)  s_b2[tid] = b2[tid];

    // warp-local roles: warp owns pixels 16*wid .. 16*wid+15
    const int pl    = lane & 15;          // pixel within warp
    const int chalf = lane >> 4;          // channel half (0..1)
    const int c0    = chalf * 8;
    const int p     = 16 * wid + pl;      // pixel within tile
    const int lx    = p & 31;
    const int ly    = p >> 5;

    const uint32_t WA  = sb32 + SM_A1 + (uint32_t)wid * 2048;   // warp A staging
    float* wds = (float*)(smem + SM_DS + wid * 1280);           // warp ds staging
    const uint32_t W1S = sb32 + SM_W1;
    const uint32_t W2S = sb32 + SM_W2;

    const int amat  = lane >> 3;
    const int arow_off = (lane & 7) + 8 * (amat & 1);
    const int acol_off = 8 * (amat >> 1);
    const int brow_off = (lane & 7) + 8 * (amat >> 1);
    const int bcol_off = 8 * (amat & 1);

    // balanced contiguous tile range: 200 CTAs x 28 + 96 CTAs x 27 = 8192
    const int bid  = (int)blockIdx.x;
    const int cnt  = 27 + (bid < 200 ? 1 : 0);
    const int base = bid * 27 + (bid < 200 ? bid : 200);

    prefetch_tile(sb32 + SM_TILE0, base, state, tid);

#pragma unroll 1
    for (int t = 0; t < cnt; t++) {
        const int tg = base + t;
        const int b  = tg >> 9;
        const int rr = tg & 511;
        const int by = (rr >> 3) * 4;
        const int bx = (rr & 7) * 32;
        const uint32_t tile_off = (t & 1) ? SM_TILE1 : SM_TILE0;
        const float* s_tile = (const float*)(smem + tile_off);

        CP_WAIT0();
        __syncthreads();   // B1 (only CTA barrier): tile ready; prev-tile reads done

        // ---- perception: this thread's 8 channels of its pixel ----
        float a[24];
        float sv[8];
#pragma unroll
        for (int i = 0; i < 8; i++) {
            const float* tp = s_tile + (c0 + i) * 204;
            const float a00 = tp[(ly + 0) * 34 + lx + 0];
            const float a01 = tp[(ly + 0) * 34 + lx + 1];
            const float a02 = tp[(ly + 0) * 34 + lx + 2];
            const float a10 = tp[(ly + 1) * 34 + lx + 0];
            const float a11 = tp[(ly + 1) * 34 + lx + 1];
            const float a12 = tp[(ly + 1) * 34 + lx + 2];
            const float a20 = tp[(ly + 2) * 34 + lx + 0];
            const float a21 = tp[(ly + 2) * 34 + lx + 1];
            const float a22 = tp[(ly + 2) * 34 + lx + 2];
            a[3 * i + 0] = (a02 - a00) + 2.0f * (a12 - a10) + (a22 - a20);
            a[3 * i + 1] = (a20 - a00) + 2.0f * (a21 - a01) + (a22 - a02);
            a[3 * i + 2] = a11;
            sv[i] = a11;
        }
        // store 12 f16x2 pairs into warp-private A staging (row=pl, 128B pitch, SW128)
        {
            const uint32_t rowb = (uint32_t)pl * 128;
#pragma unroll
            for (int j = 0; j < 12; j++) {
                const uint32_t sw = SW128(rowb + (uint32_t)(chalf * 12 + j) * 4);
                *(uint32_t*)(smem + SM_A1 + wid * 2048 + sw) = pack_f16x2(a[2 * j], a[2 * j + 1]);
            }
        }

        if (t + 1 < cnt)
            prefetch_tile(sb32 + ((t & 1) ? SM_TILE0 : SM_TILE1), tg + 1, state, tid);

        __syncwarp();   // A staging visible within warp

        // ---- GEMM1: h[16 x 128] = A[16 x 48] * w1^T (full N per warp) ----
        float acc[16][4];
#pragma unroll
        for (int nt = 0; nt < 16; nt++)
#pragma unroll
            for (int i = 0; i < 4; i++) acc[nt][i] = 0.0f;

#pragma unroll
        for (int ks = 0; ks < 3; ks++) {
            uint32_t af[4];
            const uint32_t abyte = (uint32_t)(arow_off * 128 + (ks * 16 + acol_off) * 2);
            LDSM4(af[0], af[1], af[2], af[3], WA + SW128(abyte));
#pragma unroll
            for (int ntp = 0; ntp < 8; ntp++) {
                const uint32_t bbyte = (uint32_t)((ntp * 16 + brow_off) * 128
                                                  + (ks * 16 + bcol_off) * 2);
                uint32_t b0, b1, b2, b3;
                LDSM4(b0, b1, b2, b3, W1S + SW128(bbyte));
                MMAF16(acc[2 * ntp],     af[0], af[1], af[2], af[3], b0, b1);
                MMAF16(acc[2 * ntp + 1], af[0], af[1], af[2], af[3], b2, b3);
            }
        }

        // ---- GEMM2: ds[16 x 16] = relu(h+b1)_f16 * w2^T (full K per warp) ----
        float dsv[2][4];
#pragma unroll
        for (int nt = 0; nt < 2; nt++)
#pragma unroll
            for (int i = 0; i < 4; i++) dsv[nt][i] = 0.0f;

#pragma unroll
        for (int ks = 0; ks < 8; ks++) {
            uint32_t ah[4];
#pragma unroll
            for (int j = 0; j < 2; j++) {
                const float* c = acc[2 * ks + j];
                const int col = 16 * ks + 8 * j + 2 * (lane & 3);
                const float bb0 = s_b1[col], bb1 = s_b1[col + 1];
                const float v0 = fmaxf(c[0] + bb0, 0.0f);
                const float v1 = fmaxf(c[1] + bb1, 0.0f);
                const float v2 = fmaxf(c[2] + bb0, 0.0f);
                const float v3 = fmaxf(c[3] + bb1, 0.0f);
                ah[2 * j]     = pack_f16x2(v0, v1);
                ah[2 * j + 1] = pack_f16x2(v2, v3);
            }
            const uint32_t bbyte = (uint32_t)(brow_off * 256 + (ks * 16 + bcol_off) * 2);
            uint32_t bh[4];
            LDSM4(bh[0], bh[1], bh[2], bh[3], W2S + SWW2(bbyte));
            MMAF16(dsv[0], ah[0], ah[1], ah[2], ah[3], bh[0], bh[1]);
            MMAF16(dsv[1], ah[0], ah[1], ah[2], ah[3], bh[2], bh[3]);
        }

        // ---- warp-local ds exchange (16 rows x 16 ch, pitch 18 floats) ----
        {
            const int r0 = lane >> 2;
            const int cc = 2 * (lane & 3);
#pragma unroll
            for (int nt = 0; nt < 2; nt++) {
                wds[r0 * DS_PITCH + 8 * nt + cc]           = dsv[nt][0];
                wds[r0 * DS_PITCH + 8 * nt + cc + 1]       = dsv[nt][1];
                wds[(r0 + 8) * DS_PITCH + 8 * nt + cc]     = dsv[nt][2];
                wds[(r0 + 8) * DS_PITCH + 8 * nt + cc + 1] = dsv[nt][3];
            }
        }
        __syncwarp();

        // ---- epilogue: this thread's 8 channels of its pixel ----
        const int px = bx + lx;
        const int py = by + ly;
        const float* rb = rand_u + (size_t)b * CH * HH * WW;
        float* ob = out + (size_t)b * CH * HH * WW;
        const float* dsrow = wds + pl * DS_PITCH + c0;
#pragma unroll
        for (int i = 0; i < 8; i++) {
            const int c = c0 + i;
            const int idx = (c * HH + py) * WW + px;
            const float m  = (rb[idx] < 0.5f) ? 1.0f : 0.0f;
            const float ds = dsrow[i] + s_b2[c];
            const float ns = fmaf(ds, m, sv[i]);
            ob[idx] = ns;
            if (c == 3) g_alpha[((size_t)b * HH + py) * WW + px] = ns;
        }
    }
}

// Pass 2: 3x3 max-pool of alpha -> aliveness; zero dead pixels in-place.
__global__ __launch_bounds__(256) void nca_alive_kernel(float* __restrict__ out)
{
    const int gidx = blockIdx.x * blockDim.x + threadIdx.x;
    if (gidx >= BATCH * HH * WW) return;
    const int px = gidx & (WW - 1);
    const int py = (gidx >> 8) & (HH - 1);
    const int b  = gidx >> 16;

    const float* ap = g_alpha + (size_t)b * HH * WW;
    float m = -3.402823466e38f;
#pragma unroll
    for (int dy = -1; dy <= 1; dy++) {
        const int yy = py + dy;
        if (yy < 0 || yy >= HH) continue;
#pragma unroll
        for (int dx = -1; dx <= 1; dx++) {
            const int xx = px + dx;
            if (xx < 0 || xx >= WW) continue;
            m = fmaxf(m, ap[yy * WW + xx]);
        }
    }
    if (!(m > 0.1f)) {
        float* ob = out + (size_t)b * CH * HH * WW + py * WW + px;
#pragma unroll
        for (int c = 0; c < CH; c++) ob[c * HH * WW] = 0.0f;
    }
}

extern "C" void kernel_launch(void* const* d_in, const int* in_sizes, int n_in,
                              void* d_out, int out_size)
{
    const float* state  = (const float*)d_in[0];
    const float* rand_u = (const float*)d_in[1];
    const float* w1 = (const float*)d_in[3];
    const float* b1 = (const float*)d_in[4];
    const float* w2 = (const float*)d_in[5];
    const float* b2 = (const float*)d_in[6];
    float* out = (float*)d_out;

    cudaFuncSetAttribute(nca_main_kernel, cudaFuncAttributeMaxDynamicSharedMemorySize, SM_TOTAL);
    nca_main_kernel<<<NCTA, BDIM, SM_TOTAL>>>(state, rand_u, w1, b1, w2, b2, out);

    const int npix = BATCH * HH * WW;
    nca_alive_kernel<<<(npix + 255) / 256, 256>>>(out);
}